// round 6
// baseline (speedup 1.0000x reference)
#include <cuda_runtime.h>
#include <cstdint>
#include <math.h>

// Problem constants (fixed shapes from reference)
#define NK 1024            // num embeddings
#define ND 256             // embedding dim
#define HW 1024            // H*W = 32*32
#define NB 32              // batch
#define NN 32768           // N = NB*HW
#define OUT_ELEMS 8388608  // NB*ND*HW

// ---------------- device scratch (no allocations allowed) ----------------
__device__ alignas(16) float g_Et[ND * NK];     // transposed codebook [d][k]
__device__ alignas(16) float g_enorm[NK];       // ||e_k||^2
__device__ alignas(16) float g_S[NN];           // ||x_n||^2, reference rounding order
__device__ int   g_counts[NK];
__device__ int   g_indices[NN];
__device__ float g_partials[256];               // per-block SSE partials (deterministic)

// ---------------- f32x2 packed-FMA helpers (sm_103a) ----------------
// Each 32-bit lane behaves exactly like scalar fma.rn.f32 -> a packed lane is a
// bit-exact sequential fused-FMA chain (matches Eigen gebp accumulation).
__device__ __forceinline__ unsigned long long pack2(float x) {
    unsigned long long r;
    asm("mov.b64 %0, {%1, %1};" : "=l"(r) : "f"(x));
    return r;
}
__device__ __forceinline__ void ffma2(unsigned long long& d,
                                      unsigned long long a,
                                      unsigned long long b) {
    asm("fma.rn.f32x2 %0, %1, %2, %0;" : "+l"(d) : "l"(a), "l"(b));
}
__device__ __forceinline__ void unpack2(unsigned long long v, float& lo, float& hi) {
    asm("mov.b64 {%0, %1}, %2;" : "=f"(lo), "=f"(hi) : "l"(v));
}

// ================= kernel 0: transpose E, code norms, zero counts =================
// esq ordering error (~1e-11) is negligible vs the ulp(256) lattice; any order OK.
__global__ __launch_bounds__(256)
void prep_kernel(const float* __restrict__ E) {
    const int k = blockIdx.x;      // 0..1023
    const int d = threadIdx.x;     // 0..255
    float v = E[k * ND + d];
    g_Et[d * NK + k] = v;

    float s = __fmul_rn(v, v);
    #pragma unroll
    for (int o = 16; o > 0; o >>= 1) s += __shfl_xor_sync(0xffffffffu, s, o);
    __shared__ float ws[8];
    if ((threadIdx.x & 31) == 0) ws[threadIdx.x >> 5] = s;
    __syncthreads();
    if (threadIdx.x == 0) {
        float t = 0.f;
        #pragma unroll
        for (int w = 0; w < 8; w++) t += ws[w];
        g_enorm[k] = t;
        g_counts[k] = 0;
    }
}

// ================= kernel 0b: row norms ||x_n||^2, reference bit order =================
// XLA:CPU eager: mul op rounds squares, reduce op is a strict sequential scalar
// add chain over d = 0..255. Emulate exactly: acc = fadd(acc, fmul(x,x)).
__global__ __launch_bounds__(256)
void rowsq_kernel(const float* __restrict__ X) {
    const int n = blockIdx.x * 256 + threadIdx.x;   // 0..32767
    const int b = n >> 10;
    const int hw = n & 1023;
    const float* p = X + (size_t)b * (ND * HW) + hw;
    float acc = 0.f;
    #pragma unroll 8
    for (int d = 0; d < ND; d++) {
        const float v = __ldg(p + (size_t)d * HW);
        acc = __fadd_rn(acc, __fmul_rn(v, v));      // strict sequential chain
    }
    g_S[n] = acc;
}

// ================= kernel 1: fused distance GEMM + argmin =================
// Grid: 256 CTAs, each owns 128 consecutive spatial positions (never crosses batch).
// CTA tile: BM=128 rows x BN=128 codes, BK=32 over D. 16x16 threads, 8x8 microtile.
// dot accumulated as a single sequential fused-FMA chain over d (Eigen-exact),
// dist = fl( fl(S + esq) - 2*dot )  -> same fp32 lattice as the reference.
__global__ __launch_bounds__(256, 2)
void argmin_kernel(const float* __restrict__ X) {
    __shared__ union {
        struct { float Xs[32][128]; float Es[32][128]; } t;   // GEMM tiles (32 KB)
        struct { float v[128][16]; int idx[128][16]; } red;   // final reduction
    } sm;

    const int tid = threadIdx.x;
    const int tx = tid & 15;            // column group (8 codes)
    const int ty = tid >> 4;            // row group (8 rows)
    const int row0 = blockIdx.x * 128;
    const int b   = row0 >> 10;
    const int hw0 = row0 & 1023;
    const float* Xbase = X + (size_t)b * (ND * HW) + hw0;

    float Srow[8];
    #pragma unroll
    for (int i = 0; i < 8; i++) Srow[i] = __ldg(&g_S[row0 + ty * 8 + i]);

    float bestv[8];
    int   besti[8];
    #pragma unroll
    for (int i = 0; i < 8; i++) { bestv[i] = 3.4e38f; besti[i] = 0; }

    for (int ct = 0; ct < 8; ct++) {           // code tiles of 128
        const int k0 = ct * 128;
        unsigned long long acc[8][4];          // 8 rows x 4 col-pairs (f32x2)
        #pragma unroll
        for (int i = 0; i < 8; i++)
            #pragma unroll
            for (int j = 0; j < 4; j++) acc[i][j] = 0ULL;

        for (int dk = 0; dk < 8; dk++) {       // D chunks of 32, ascending d
            const int d0 = dk * 32;
            // Cooperative tile loads: both X and Et are contiguous along the
            // 128-wide fast axis -> fully coalesced float4, conflict-free stores.
            #pragma unroll
            for (int it = 0; it < 4; it++) {
                int idx4 = tid + it * 256;           // 0..1023
                int c  = idx4 >> 5;                  // dim within chunk 0..31
                int r4 = (idx4 & 31) << 2;           // 0..124
                float4 xv = __ldg(reinterpret_cast<const float4*>(Xbase + (size_t)(d0 + c) * HW + r4));
                *reinterpret_cast<float4*>(&sm.t.Xs[c][r4]) = xv;
                float4 ev = __ldg(reinterpret_cast<const float4*>(&g_Et[(size_t)(d0 + c) * NK + k0 + r4]));
                *reinterpret_cast<float4*>(&sm.t.Es[c][r4]) = ev;
            }
            __syncthreads();

            #pragma unroll 4
            for (int kk = 0; kk < 32; kk++) {    // ascending within chunk
                const float4 xa = *reinterpret_cast<const float4*>(&sm.t.Xs[kk][ty * 8]);
                const float4 xb = *reinterpret_cast<const float4*>(&sm.t.Xs[kk][ty * 8 + 4]);
                const ulonglong2 ea = *reinterpret_cast<const ulonglong2*>(&sm.t.Es[kk][tx * 8]);
                const ulonglong2 eb = *reinterpret_cast<const ulonglong2*>(&sm.t.Es[kk][tx * 8 + 4]);
                const float xs[8] = {xa.x, xa.y, xa.z, xa.w, xb.x, xb.y, xb.z, xb.w};
                const unsigned long long es[4] = {ea.x, ea.y, eb.x, eb.y};
                #pragma unroll
                for (int i = 0; i < 8; i++) {
                    const unsigned long long xp = pack2(xs[i]);
                    #pragma unroll
                    for (int j = 0; j < 4; j++) ffma2(acc[i][j], xp, es[j]);
                }
            }
            __syncthreads();
        }

        // Fold this code tile into the running per-row argmin, on the
        // reference's fp32 lattice: fl( fl(S + esq_k) - 2*dot ).
        const float4 en0 = __ldg(reinterpret_cast<const float4*>(&g_enorm[k0 + tx * 8]));
        const float4 en1 = __ldg(reinterpret_cast<const float4*>(&g_enorm[k0 + tx * 8 + 4]));
        const float en[8] = {en0.x, en0.y, en0.z, en0.w, en1.x, en1.y, en1.z, en1.w};
        #pragma unroll
        for (int i = 0; i < 8; i++) {
            #pragma unroll
            for (int jp = 0; jp < 4; jp++) {
                float dlo, dhi;
                unpack2(acc[i][jp], dlo, dhi);
                const int c0 = k0 + tx * 8 + jp * 2;
                const float t0 = __fadd_rn(Srow[i], en[jp * 2]);
                const float t1 = __fadd_rn(Srow[i], en[jp * 2 + 1]);
                const float dist0 = __fsub_rn(t0, 2.0f * dlo);   // 2x exact
                const float dist1 = __fsub_rn(t1, 2.0f * dhi);
                // ascending column order + strict < keeps the FIRST minimum
                if (dist0 < bestv[i]) { bestv[i] = dist0; besti[i] = c0; }
                if (dist1 < bestv[i]) { bestv[i] = dist1; besti[i] = c0 + 1; }
            }
        }
    }

    // Cross-tx reduction per row; tie-break on index to match jnp.argmin
    // "first minimum" semantics (ties are now real due to lattice rounding).
    __syncthreads();
    #pragma unroll
    for (int i = 0; i < 8; i++) {
        sm.red.v[ty * 8 + i][tx]   = bestv[i];
        sm.red.idx[ty * 8 + i][tx] = besti[i];
    }
    __syncthreads();
    if (tid < 128) {
        float bv = sm.red.v[tid][0];
        int   bi = sm.red.idx[tid][0];
        #pragma unroll
        for (int t = 1; t < 16; t++) {
            const float v = sm.red.v[tid][t];
            const int  ix = sm.red.idx[tid][t];
            if (v < bv || (v == bv && ix < bi)) { bv = v; bi = ix; }
        }
        g_indices[row0 + tid] = bi;
        atomicAdd(&g_counts[bi], 1);   // integer atomic: deterministic
    }
}

// ================= kernel 2: gather + straight-through output + SSE =================
__global__ __launch_bounds__(256)
void epilogue_kernel(const float* __restrict__ X, float* __restrict__ out) {
    __shared__ int idxs[128];
    __shared__ float ws[8];
    const int tid = threadIdx.x;
    const int row0 = blockIdx.x * 128;
    const int b   = row0 >> 10;
    const int hw0 = row0 & 1023;
    const size_t base = (size_t)b * (ND * HW) + hw0;

    if (tid < 128) idxs[tid] = g_indices[row0 + tid];
    __syncthreads();

    float acc = 0.f;
    #pragma unroll 4
    for (int it = 0; it < 32; it++) {
        const int pos = it * 256 + tid;      // 0..8191 float4 slots
        const int d   = pos >> 5;            // 0..255
        const int r4  = (pos & 31) << 2;     // 0..124
        const float4 x = __ldg(reinterpret_cast<const float4*>(X + base + (size_t)d * HW + r4));
        float4 q;
        q.x = g_Et[d * NK + idxs[r4 + 0]];
        q.y = g_Et[d * NK + idxs[r4 + 1]];
        q.z = g_Et[d * NK + idxs[r4 + 2]];
        q.w = g_Et[d * NK + idxs[r4 + 3]];
        // reference: diff = fl(q - x); out = fl(x + diff)
        const float dx = __fsub_rn(q.x, x.x);
        const float dy = __fsub_rn(q.y, x.y);
        const float dz = __fsub_rn(q.z, x.z);
        const float dw = __fsub_rn(q.w, x.w);
        acc += dx * dx + dy * dy + dz * dz + dw * dw;
        float4 o;
        o.x = __fadd_rn(x.x, dx); o.y = __fadd_rn(x.y, dy);
        o.z = __fadd_rn(x.z, dz); o.w = __fadd_rn(x.w, dw);
        *reinterpret_cast<float4*>(out + base + (size_t)d * HW + r4) = o;
    }
    #pragma unroll
    for (int o = 16; o > 0; o >>= 1) acc += __shfl_xor_sync(0xffffffffu, acc, o);
    if ((tid & 31) == 0) ws[tid >> 5] = acc;
    __syncthreads();
    if (tid == 0) {
        float t = 0.f;
        #pragma unroll
        for (int w = 0; w < 8; w++) t += ws[w];
        g_partials[blockIdx.x] = t;   // plain store: deterministic reduction
    }
}

// ================= kernel 3: loss + perplexity scalars =================
__global__ __launch_bounds__(256)
void finalize_kernel(float* __restrict__ out, int out_size) {
    __shared__ float ws[8];
    const int tid = threadIdx.x;

    // --- SSE over 256 partials ---
    float s = g_partials[tid];
    #pragma unroll
    for (int o = 16; o > 0; o >>= 1) s += __shfl_xor_sync(0xffffffffu, s, o);
    if ((tid & 31) == 0) ws[tid >> 5] = s;
    __syncthreads();
    float sse = 0.f;
    if (tid == 0) {
        #pragma unroll
        for (int w = 0; w < 8; w++) sse += ws[w];
    }
    __syncthreads();

    // --- entropy over counts (counts/N is exact: /2^15) ---
    float ent = 0.f;
    #pragma unroll
    for (int k = tid; k < NK; k += 256) {
        const float p = (float)g_counts[k] * (1.0f / (float)NN);
        ent += p * logf(p + 1e-10f);
    }
    #pragma unroll
    for (int o = 16; o > 0; o >>= 1) ent += __shfl_xor_sync(0xffffffffu, ent, o);
    if ((tid & 31) == 0) ws[tid >> 5] = ent;
    __syncthreads();
    if (tid == 0) {
        float e = 0.f;
        #pragma unroll
        for (int w = 0; w < 8; w++) e += ws[w];
        if (out_size >= OUT_ELEMS + 2) {
            // loss = q_latent + 0.25*e_latent; both equal mean((q-x)^2) in value
            out[OUT_ELEMS]     = 1.25f * sse / (float)OUT_ELEMS;
            out[OUT_ELEMS + 1] = expf(-e);
        }
    }
}

// ================= launcher =================
extern "C" void kernel_launch(void* const* d_in, const int* in_sizes, int n_in,
                              void* d_out, int out_size) {
    const float* X = (const float*)d_in[0];   // inputs [32,256,32,32]
    const float* E = (const float*)d_in[1];   // embedding_weight [1024,256]
    float* out = (float*)d_out;

    prep_kernel<<<NK, 256>>>(E);
    rowsq_kernel<<<NN / 256, 256>>>(X);
    argmin_kernel<<<NN / 128, 256>>>(X);
    epilogue_kernel<<<NN / 128, 256>>>(X, out);
    finalize_kernel<<<1, 256>>>(out, out_size);
}